// round 4
// baseline (speedup 1.0000x reference)
#include <cuda_runtime.h>
#include <cuda_bf16.h>

#define DEPTH     4096
#define NTHREADS  256          /* one thread per 16-sample Haar tree */
#define HKC       0.70710678118654752440f

// Fully-register-resident wavelet layer. One CTA per row, one thread per
// 16 consecutive samples.
//
//  dec:  thread t computes y[16t..16t+16) = x*vec_b, runs the 4-scale Haar
//        butterfly in registers, writes c = [cA4|d4|d3|d2|d1] to smem.
//  rec:  out[i] = s[i]*h*(h*(h*(h*(g[i>>4] +- g[2048+(i>>4)]) +- g[1024+(i>>3)])
//                 +- g[512+(i>>2)]) +- g[256+(i>>1)]),  g[j]=vec_g[j]*c[perm[j]],
//        signs from bits 3..0 of i. Thread t needs exactly 16 gathered values.
__global__ __launch_bounds__(NTHREADS)
void wavelet_fused_kernel(const float* __restrict__ x,
                          const float* __restrict__ vec_b,
                          const float* __restrict__ vec_g,
                          const float* __restrict__ vec_s,
                          const int*  __restrict__ perm,
                          float* __restrict__ out)
{
    __shared__ float c[DEPTH];                     // 16 KB

    const int row = blockIdx.x;
    const int t   = threadIdx.x;

    // ---- prefetch all per-thread broadcast data (overlaps with everything)
    const int  p0  = __ldg(&perm[t]);
    const int  p1  = __ldg(&perm[2048 + t]);
    const int2 p2  = __ldg(reinterpret_cast<const int2*>(&perm[1024 + 2*t]));
    const int4 p3  = __ldg(reinterpret_cast<const int4*>(&perm[512  + 4*t]));
    const int4 p4a = __ldg(reinterpret_cast<const int4*>(&perm[256  + 8*t]));
    const int4 p4b = __ldg(reinterpret_cast<const int4*>(&perm[256  + 8*t + 4]));

    const float  w0  = __ldg(&vec_g[t]);
    const float  w1  = __ldg(&vec_g[2048 + t]);
    const float2 w2  = __ldg(reinterpret_cast<const float2*>(&vec_g[1024 + 2*t]));
    const float4 w3  = __ldg(reinterpret_cast<const float4*>(&vec_g[512  + 4*t]));
    const float4 w4a = __ldg(reinterpret_cast<const float4*>(&vec_g[256  + 8*t]));
    const float4 w4b = __ldg(reinterpret_cast<const float4*>(&vec_g[256  + 8*t + 4]));

    // ================= decomposition (registers only) =====================
    float y[16];
    {
        const float4* x4 = reinterpret_cast<const float4*>(x + (size_t)row * DEPTH);
        const float4* b4 = reinterpret_cast<const float4*>(vec_b);
        #pragma unroll
        for (int j = 0; j < 4; ++j) {
            float4 xv = __ldcs(&x4[4 * t + j]);    // streaming read
            float4 bv = __ldg (&b4[4 * t + j]);
            y[4*j+0] = xv.x * bv.x;  y[4*j+1] = xv.y * bv.y;
            y[4*j+2] = xv.z * bv.z;  y[4*j+3] = xv.w * bv.w;
        }
    }

    float s1[8], d1[8];
    #pragma unroll
    for (int p = 0; p < 8; ++p) {
        s1[p] = y[2*p] + y[2*p+1];
        d1[p] = (y[2*p] - y[2*p+1]) * HKC;
    }
    float s2[4], d2[4];
    #pragma unroll
    for (int q = 0; q < 4; ++q) {
        s2[q] = s1[2*q] + s1[2*q+1];
        d2[q] = (s1[2*q] - s1[2*q+1]) * (HKC * HKC);
    }
    float s3[2], d3[2];
    #pragma unroll
    for (int r = 0; r < 2; ++r) {
        s3[r] = s2[2*r] + s2[2*r+1];
        d3[r] = (s2[2*r] - s2[2*r+1]) * (HKC * HKC * HKC);
    }
    const float h4  = HKC * HKC * HKC * HKC;
    const float cA4 = (s3[0] + s3[1]) * h4;
    const float d4  = (s3[0] - s3[1]) * h4;

    // c = [cA4(256) | d4(256) | d3(512) | d2(1024) | d1(2048)]
    c[t]        = cA4;
    c[256 + t]  = d4;
    reinterpret_cast<float2*>(&c[512  + 2*t])[0] = make_float2(d3[0], d3[1]);
    reinterpret_cast<float4*>(&c[1024 + 4*t])[0] = make_float4(d2[0], d2[1], d2[2], d2[3]);
    reinterpret_cast<float4*>(&c[2048 + 8*t])[0] = make_float4(d1[0], d1[1], d1[2], d1[3]);
    reinterpret_cast<float4*>(&c[2048 + 8*t])[1] = make_float4(d1[4], d1[5], d1[6], d1[7]);

    __syncthreads();

    // ================= reconstruction (direct formula) ====================
    const float G0 = w0 * c[p0];
    const float G1 = w1 * c[p1];
    float G2[2], G3[4], G4[8];
    G2[0] = w2.x * c[p2.x];  G2[1] = w2.y * c[p2.y];
    G3[0] = w3.x * c[p3.x];  G3[1] = w3.y * c[p3.y];
    G3[2] = w3.z * c[p3.z];  G3[3] = w3.w * c[p3.w];
    G4[0] = w4a.x * c[p4a.x];  G4[1] = w4a.y * c[p4a.y];
    G4[2] = w4a.z * c[p4a.z];  G4[3] = w4a.w * c[p4a.w];
    G4[4] = w4b.x * c[p4b.x];  G4[5] = w4b.y * c[p4b.y];
    G4[6] = w4b.z * c[p4b.z];  G4[7] = w4b.w * c[p4b.w];

    // inverse butterfly in registers
    const float u1p = (G0 + G1) * HKC;
    const float u1m = (G0 - G1) * HKC;
    float u2[4];
    u2[0] = (u1p + G2[0]) * HKC;  u2[1] = (u1p - G2[0]) * HKC;
    u2[2] = (u1m + G2[1]) * HKC;  u2[3] = (u1m - G2[1]) * HKC;
    float u3[8];
    #pragma unroll
    for (int j = 0; j < 8; ++j) {
        float g = G3[j >> 1];
        u3[j] = (u2[j >> 1] + ((j & 1) ? -g : g)) * HKC;
    }

    // scale by vec_s and store 64B per thread (4x float4)
    {
        float4* out4 = reinterpret_cast<float4*>(out + (size_t)row * DEPTH) + 4 * t;
        const float4* s4 = reinterpret_cast<const float4*>(vec_s) + 4 * t;
        #pragma unroll
        for (int j = 0; j < 4; ++j) {
            float4 sv = __ldg(&s4[j]);
            int k0 = 4 * j;
            float4 r;
            r.x = (u3[(k0+0) >> 1] + G4[(k0+0) >> 1]) * HKC * sv.x;
            r.y = (u3[(k0+1) >> 1] - G4[(k0+1) >> 1]) * HKC * sv.y;
            r.z = (u3[(k0+2) >> 1] + G4[(k0+2) >> 1]) * HKC * sv.z;
            r.w = (u3[(k0+3) >> 1] - G4[(k0+3) >> 1]) * HKC * sv.w;
            __stcs(&out4[j], r);
        }
    }
}

extern "C" void kernel_launch(void* const* d_in, const int* in_sizes, int n_in,
                              void* d_out, int out_size)
{
    const float* x     = (const float*)d_in[0];
    const float* vec_b = (const float*)d_in[1];
    const float* vec_g = (const float*)d_in[2];
    const float* vec_s = (const float*)d_in[3];
    const int*   perm  = (const int*)  d_in[4];
    float* out = (float*)d_out;

    const int batch = in_sizes[0] / DEPTH;   // 8192
    wavelet_fused_kernel<<<batch, NTHREADS>>>(x, vec_b, vec_g, vec_s, perm, out);
}

// round 6
// speedup vs baseline: 1.5417x; 1.5417x over previous
#include <cuda_runtime.h>
#include <cuda_bf16.h>

#define DEPTH        4096
#define NTHREADS     512     /* one thread per 8 samples */
#define ROWS_PER_CTA 8
#define HKC          0.70710678118654752440f

// Multi-row register-resident wavelet layer.
// Thread t owns samples/outputs [8t, 8t+8). Broadcast data (perm, vec_g,
// vec_b, vec_s) is loaded into registers ONCE per CTA and reused for 8 rows.
//
// dec:  y = x*vec_b -> 4-scale Haar butterfly in regs (scale 4 via shfl_xor
//       across thread pairs) -> c = [cA4|d4|d3|d2|d1] in smem (coalesced).
// rec:  9 gathered values g[j] = vec_g[j]*c[perm[j]] per thread, direct
//       inverse butterfly, signs per reference's overlapping-slice map:
//       coeff_lst = [g[0:256], g[2048:2304], g[1024:1536], g[512:1536], g[256:2304]]
__global__ __launch_bounds__(NTHREADS, 2)
void wavelet_fused_kernel(const float* __restrict__ x,
                          const float* __restrict__ vec_b,
                          const float* __restrict__ vec_g,
                          const float* __restrict__ vec_s,
                          const int*  __restrict__ perm,
                          float* __restrict__ out)
{
    __shared__ float c[2][DEPTH];                 // 32 KB double buffer

    const int t  = threadIdx.x;
    const int th = t >> 1;                        // thread-pair index

    // ---- one-time persistent loads (amortized over 8 rows) ---------------
    const int  p0 = __ldg(&perm[th]);
    const int  p1 = __ldg(&perm[2048 + th]);
    const int  p2 = __ldg(&perm[1024 + t]);
    const int2 p3 = __ldg(reinterpret_cast<const int2*>(&perm[512 + 2 * t]));
    const int4 p4 = __ldg(reinterpret_cast<const int4*>(&perm[256 + 4 * t]));

    const float  w0 = __ldg(&vec_g[th]);
    const float  w1 = __ldg(&vec_g[2048 + th]);
    const float  w2 = __ldg(&vec_g[1024 + t]);
    const float2 w3 = __ldg(reinterpret_cast<const float2*>(&vec_g[512 + 2 * t]));
    const float4 w4 = __ldg(reinterpret_cast<const float4*>(&vec_g[256 + 4 * t]));

    const float4 bv0 = __ldg(reinterpret_cast<const float4*>(&vec_b[8 * t]));
    const float4 bv1 = __ldg(reinterpret_cast<const float4*>(&vec_b[8 * t + 4]));
    const float4 sv0 = __ldg(reinterpret_cast<const float4*>(&vec_s[8 * t]));
    const float4 sv1 = __ldg(reinterpret_cast<const float4*>(&vec_s[8 * t + 4]));

    const float H2 = HKC * HKC;
    const float H3 = H2 * HKC;
    const float H4 = H2 * H2;

    const size_t base = (size_t)blockIdx.x * ROWS_PER_CTA * DEPTH;

    #pragma unroll 1
    for (int r = 0; r < ROWS_PER_CTA; ++r) {
        float* cb = c[r & 1];

        // ---- load 8 samples, apply vec_b ---------------------------------
        const float4* x4 = reinterpret_cast<const float4*>(x + base + (size_t)r * DEPTH);
        float4 xv0 = __ldcs(&x4[2 * t]);
        float4 xv1 = __ldcs(&x4[2 * t + 1]);
        const float y0 = xv0.x * bv0.x, y1 = xv0.y * bv0.y;
        const float y2 = xv0.z * bv0.z, y3 = xv0.w * bv0.w;
        const float y4 = xv1.x * bv1.x, y5 = xv1.y * bv1.y;
        const float y6 = xv1.z * bv1.z, y7 = xv1.w * bv1.w;

        // ---- decomposition butterfly (registers) -------------------------
        const float s1a = y0 + y1, s1b = y2 + y3, s1c = y4 + y5, s1d = y6 + y7;
        float4 d1;
        d1.x = (y0 - y1) * HKC;  d1.y = (y2 - y3) * HKC;
        d1.z = (y4 - y5) * HKC;  d1.w = (y6 - y7) * HKC;
        const float s2a = s1a + s1b, s2b = s1c + s1d;
        float2 d2;
        d2.x = (s1a - s1b) * H2;  d2.y = (s1c - s1d) * H2;
        const float s3 = s2a + s2b;
        const float d3 = (s2a - s2b) * H3;
        const float s3o = __shfl_xor_sync(0xffffffffu, s3, 1);

        // c = [cA4(256) | d4(256) | d3(512) | d2(1024) | d1(2048)]
        *reinterpret_cast<float4*>(&cb[2048 + 4 * t]) = d1;
        *reinterpret_cast<float2*>(&cb[1024 + 2 * t]) = d2;
        cb[512 + t] = d3;
        if (t & 1) cb[256 + th] = (s3o - s3) * H4;     // d4  (lo - hi)
        else       cb[th]       = (s3 + s3o) * H4;     // cA4 (lo + hi)

        __syncthreads();

        // ---- gather (9 random LDS) + inverse butterfly -------------------
        const float G0  = w0  * cb[p0];
        const float G1  = w1  * cb[p1];
        const float G2  = w2  * cb[p2];
        const float G3x = w3.x * cb[p3.x];
        const float G3y = w3.y * cb[p3.y];
        const float G4x = w4.x * cb[p4.x];
        const float G4y = w4.y * cb[p4.y];
        const float G4z = w4.z * cb[p4.z];
        const float G4w = w4.w * cb[p4.w];

        const float r1  = ((t & 1) ? (G0 - G1) : (G0 + G1)) * HKC;
        const float r2a = (r1 + G2) * HKC;
        const float r2b = (r1 - G2) * HKC;
        const float r3a = (r2a + G3x) * HKC;
        const float r3b = (r2a - G3x) * HKC;
        const float r3c = (r2b + G3y) * HKC;
        const float r3d = (r2b - G3y) * HKC;

        float4 o0, o1;
        o0.x = (r3a + G4x) * HKC * sv0.x;
        o0.y = (r3a - G4x) * HKC * sv0.y;
        o0.z = (r3b + G4y) * HKC * sv0.z;
        o0.w = (r3b - G4y) * HKC * sv0.w;
        o1.x = (r3c + G4z) * HKC * sv1.x;
        o1.y = (r3c - G4z) * HKC * sv1.y;
        o1.z = (r3d + G4w) * HKC * sv1.z;
        o1.w = (r3d - G4w) * HKC * sv1.w;

        float4* o4 = reinterpret_cast<float4*>(out + base + (size_t)r * DEPTH);
        __stcs(&o4[2 * t],     o0);
        __stcs(&o4[2 * t + 1], o1);
        // no trailing sync needed: double buffer + next row's sync protects reuse
    }
}

extern "C" void kernel_launch(void* const* d_in, const int* in_sizes, int n_in,
                              void* d_out, int out_size)
{
    const float* x     = (const float*)d_in[0];
    const float* vec_b = (const float*)d_in[1];
    const float* vec_g = (const float*)d_in[2];
    const float* vec_s = (const float*)d_in[3];
    const int*   perm  = (const int*)  d_in[4];
    float* out = (float*)d_out;

    const int batch = in_sizes[0] / DEPTH;            // 8192
    wavelet_fused_kernel<<<batch / ROWS_PER_CTA, NTHREADS>>>(x, vec_b, vec_g, vec_s, perm, out);
}

// round 7
// speedup vs baseline: 1.8585x; 1.2055x over previous
#include <cuda_runtime.h>
#include <cuda_bf16.h>

#define DEPTH        4096
#define NTHREADS     512     /* one thread per 8 samples */
#define ROWS_PER_CTA 8
#define HKC          0.70710678118654752440f

// Multi-row register-resident wavelet layer with cross-row software pipelining.
// Thread t owns samples/outputs [8t, 8t+8). Broadcast data (perm, vec_g, vec_b)
// lives in registers for all 8 rows; vec_s is re-read from L1 at store time.
// Row r+1's global loads are issued before row r's butterfly so DRAM latency
// overlaps compute/barrier/gather/store.
//
// Reference slice map (reproduced exactly, incl. overlapping slices):
//   coeff_lst = [ g[0:256], g[2048:2304], g[1024:1536], g[512:1536], g[256:2304] ]
__global__ __launch_bounds__(NTHREADS, 2)
void wavelet_fused_kernel(const float* __restrict__ x,
                          const float* __restrict__ vec_b,
                          const float* __restrict__ vec_g,
                          const float* __restrict__ vec_s,
                          const int*  __restrict__ perm,
                          float* __restrict__ out)
{
    __shared__ float c[2][DEPTH];                 // 32 KB double buffer

    const int t  = threadIdx.x;
    const int th = t >> 1;                        // thread-pair index

    // ---- one-time persistent loads (amortized over 8 rows) ---------------
    const int  p0 = __ldg(&perm[th]);
    const int  p1 = __ldg(&perm[2048 + th]);
    const int  p2 = __ldg(&perm[1024 + t]);
    const int2 p3 = __ldg(reinterpret_cast<const int2*>(&perm[512 + 2 * t]));
    const int4 p4 = __ldg(reinterpret_cast<const int4*>(&perm[256 + 4 * t]));

    const float  w0 = __ldg(&vec_g[th]);
    const float  w1 = __ldg(&vec_g[2048 + th]);
    const float  w2 = __ldg(&vec_g[1024 + t]);
    const float2 w3 = __ldg(reinterpret_cast<const float2*>(&vec_g[512 + 2 * t]));
    const float4 w4 = __ldg(reinterpret_cast<const float4*>(&vec_g[256 + 4 * t]));

    const float4 bv0 = __ldg(reinterpret_cast<const float4*>(&vec_b[8 * t]));
    const float4 bv1 = __ldg(reinterpret_cast<const float4*>(&vec_b[8 * t + 4]));

    const float H2 = HKC * HKC;
    const float H3 = H2 * HKC;
    const float H4 = H2 * H2;

    const size_t base = (size_t)blockIdx.x * ROWS_PER_CTA * DEPTH;
    const float4* x4   = reinterpret_cast<const float4*>(x + base);
    float4*       o4   = reinterpret_cast<float4*>(out + base);
    const float4* sp4  = reinterpret_cast<const float4*>(vec_s) + 2 * t;

    // preload row 0
    float4 xv0 = __ldcs(&x4[2 * t]);
    float4 xv1 = __ldcs(&x4[2 * t + 1]);

    #pragma unroll 1
    for (int r = 0; r < ROWS_PER_CTA; ++r) {
        float* cb = c[r & 1];

        // ---- prefetch row r+1 (in flight during everything below) --------
        float4 xn0 = xv0, xn1 = xv1;
        if (r + 1 < ROWS_PER_CTA) {
            const float4* xr = x4 + (size_t)(r + 1) * (DEPTH / 4);
            xn0 = __ldcs(&xr[2 * t]);
            xn1 = __ldcs(&xr[2 * t + 1]);
        }

        // ---- y = x * vec_b, decomposition butterfly (registers) ----------
        const float y0 = xv0.x * bv0.x, y1 = xv0.y * bv0.y;
        const float y2 = xv0.z * bv0.z, y3 = xv0.w * bv0.w;
        const float y4 = xv1.x * bv1.x, y5 = xv1.y * bv1.y;
        const float y6 = xv1.z * bv1.z, y7 = xv1.w * bv1.w;

        const float s1a = y0 + y1, s1b = y2 + y3, s1c = y4 + y5, s1d = y6 + y7;
        float4 d1;
        d1.x = (y0 - y1) * HKC;  d1.y = (y2 - y3) * HKC;
        d1.z = (y4 - y5) * HKC;  d1.w = (y6 - y7) * HKC;
        const float s2a = s1a + s1b, s2b = s1c + s1d;
        float2 d2;
        d2.x = (s1a - s1b) * H2;  d2.y = (s1c - s1d) * H2;
        const float s3 = s2a + s2b;
        const float d3 = (s2a - s2b) * H3;
        const float s3o = __shfl_xor_sync(0xffffffffu, s3, 1);

        // c = [cA4(256) | d4(256) | d3(512) | d2(1024) | d1(2048)]
        *reinterpret_cast<float4*>(&cb[2048 + 4 * t]) = d1;
        *reinterpret_cast<float2*>(&cb[1024 + 2 * t]) = d2;
        cb[512 + t] = d3;
        if (t & 1) cb[256 + th] = (s3o - s3) * H4;     // d4  (lo - hi)
        else       cb[th]       = (s3 + s3o) * H4;     // cA4 (lo + hi)

        __syncthreads();

        // ---- gather (9 random LDS) + inverse butterfly -------------------
        const float G0  = w0  * cb[p0];
        const float G1  = w1  * cb[p1];
        const float G2  = w2  * cb[p2];
        const float G3x = w3.x * cb[p3.x];
        const float G3y = w3.y * cb[p3.y];
        const float G4x = w4.x * cb[p4.x];
        const float G4y = w4.y * cb[p4.y];
        const float G4z = w4.z * cb[p4.z];
        const float G4w = w4.w * cb[p4.w];

        // vec_s re-read (L1-resident, consumed last — latency free)
        const float4 sv0 = __ldg(&sp4[0]);
        const float4 sv1 = __ldg(&sp4[1]);

        const float r1  = ((t & 1) ? (G0 - G1) : (G0 + G1)) * HKC;
        const float r2a = (r1 + G2) * HKC;
        const float r2b = (r1 - G2) * HKC;
        const float r3a = (r2a + G3x) * HKC;
        const float r3b = (r2a - G3x) * HKC;
        const float r3c = (r2b + G3y) * HKC;
        const float r3d = (r2b - G3y) * HKC;

        float4 o0, o1;
        o0.x = (r3a + G4x) * HKC * sv0.x;
        o0.y = (r3a - G4x) * HKC * sv0.y;
        o0.z = (r3b + G4y) * HKC * sv0.z;
        o0.w = (r3b - G4y) * HKC * sv0.w;
        o1.x = (r3c + G4z) * HKC * sv1.x;
        o1.y = (r3c - G4z) * HKC * sv1.y;
        o1.z = (r3d + G4w) * HKC * sv1.z;
        o1.w = (r3d - G4w) * HKC * sv1.w;

        float4* orow = o4 + (size_t)r * (DEPTH / 4);
        __stcs(&orow[2 * t],     o0);
        __stcs(&orow[2 * t + 1], o1);

        xv0 = xn0;  xv1 = xn1;
        // no trailing sync: double buffer + next row's sync protects reuse
    }
}

extern "C" void kernel_launch(void* const* d_in, const int* in_sizes, int n_in,
                              void* d_out, int out_size)
{
    const float* x     = (const float*)d_in[0];
    const float* vec_b = (const float*)d_in[1];
    const float* vec_g = (const float*)d_in[2];
    const float* vec_s = (const float*)d_in[3];
    const int*   perm  = (const int*)  d_in[4];
    float* out = (float*)d_out;

    const int batch = in_sizes[0] / DEPTH;            // 8192
    wavelet_fused_kernel<<<batch / ROWS_PER_CTA, NTHREADS>>>(x, vec_b, vec_g, vec_s, perm, out);
}